// round 14
// baseline (speedup 1.0000x reference)
#include <cuda_runtime.h>
#include <cuda_fp16.h>
#include <cstdint>

// Problem-shape maxima (S=128 segments, lengths in [1024,3072])
#define NMAX 393216
#define S_MAX 128
#define NCH 8          // attn chunks per segment
#define CROWS 384      // rows per attn chunk (8*384 = 3072 = max len)

__device__ float g_y[NMAX];
__device__ float g_z[NMAX];
__device__ float4 g_segp[S_MAX];
__device__ int   g_offv[S_MAX];
__device__ float g_part[S_MAX * NCH * 256];
__device__ int   g_cnt[S_MAX];    // zero-init; self-resetting per call
__device__ int   g_sync0;         // monotonic arrival counter (never reset)
__device__ int   g_flag[S_MAX];   // per-segment stats-ready epoch (monotonic)

__device__ __forceinline__ float tanh_approx(float v) {
    float r;
    asm("tanh.approx.f32 %0, %1;" : "=f"(r) : "f"(v));
    return r;
}
__device__ __forceinline__ uint32_t smem_u32(const void* p) {
    uint32_t a;
    asm("{ .reg .u64 t; cvta.to.shared.u64 t, %1; cvt.u32.u64 %0, t; }" : "=r"(a) : "l"(p));
    return a;
}
__device__ __forceinline__ void ldm4(uint32_t* r, uint32_t addr) {
    asm volatile("ldmatrix.sync.aligned.m8n8.x4.shared.b16 {%0,%1,%2,%3}, [%4];"
        : "=r"(r[0]), "=r"(r[1]), "=r"(r[2]), "=r"(r[3]) : "r"(addr));
}
// f16-accumulate HMMA: C/D = 2 regs (f16x2)
__device__ __forceinline__ void mma16816h(uint32_t* c, const uint32_t* a,
                                          uint32_t b0, uint32_t b1) {
    asm volatile("mma.sync.aligned.m16n8k16.row.col.f16.f16.f16.f16 "
        "{%0,%1}, {%2,%3,%4,%5}, {%6,%7}, {%0,%1};"
        : "+r"(c[0]), "+r"(c[1])
        : "r"(a[0]), "r"(a[1]), "r"(a[2]), "r"(a[3]), "r"(b0), "r"(b1));
}
__device__ __forceinline__ void bar_pair(int id) {
    asm volatile("bar.sync %0, 64;" :: "r"(id) : "memory");
}

// ---------------------------------------------------------------------------
// ONE persistent kernel: gemm+head -> global barrier -> seg stats (per-seg
// ready flags) -> attn+out (spins only on its segment's flag).
//   Phase 1 = R13 gemm (pair-decoupled HMMA f16-accum, ldmatrix, dbuf A+B).
//   Global barrier: monotonic counter, replay-safe under graph capture.
// ---------------------------------------------------------------------------
#define XSTB 144          // x row stride, bytes (64 halves + 8 pad)
#define WSTB 528          // W1 row stride, bytes (256 halves + 8 pad)
#define WST  264          // W1 row stride, halves
#define XBUFB (128 * XSTB)           // 18432 bytes per x buffer
#define W1OFF (2 * XBUFB)            // 36864
#define FOFF  (W1OFF + 128 * WSTB)   // 104448
#define SMEM_K1 (FOFF + 512 + 1024 + 1024)

__global__ __launch_bounds__(256, 2) void fused_kernel(
    const float* __restrict__ x, const float* __restrict__ W1,
    const float* __restrict__ b1, const float* __restrict__ W2,
    const float* __restrict__ b2, const int* __restrict__ lengths,
    float* __restrict__ attn_out, float* __restrict__ out,
    int N, int ntiles, int S)
{
    extern __shared__ char smem[];
    const int tid  = threadIdx.x;
    const int lane = tid & 31;
    const int w    = tid >> 5;       // 0..7

    // ======================= PHASE 1: GEMM + HEAD =========================
    {
        half*   w1s = (half*)(smem + W1OFF);
        float*  sb1 = (float*)(smem + FOFF);
        float*  sw2 = sb1 + 128;
        float2* sEp = (float2*)(sw2 + 256);

        const int wa   = w & 3;          // pair id / A-row quarter
        const int hb   = (w >> 2) * 8;   // h-tile base (units of 8 columns)
        const int barid = 1 + wa;

        // Stage W1 transposed (h-major, k contiguous) as fp16 — once
        for (int idx = tid; idx < 256 * 128; idx += 256) {
            int k = idx >> 7, h = idx & 127;
            w1s[h * WST + k] = __float2half(W1[idx]);
        }
        if (tid < 128) sb1[tid] = b1[tid];
        sw2[tid] = W2[tid];

        const float B20 = __ldg(b2), B21 = __ldg(b2 + 1);
        const int stride = gridDim.x;
        const float4* __restrict__ x4 = (const float4*)x;

        const int rbw = wa * 32 + (w >> 2) * 16 + (lane >> 4);  // + i*2
        const int ldq = lane & 15;

        const uint32_t sbase = smem_u32(smem);
        const uint32_t aoffc = ((lane >> 3) & 1) * (8 * XSTB) + (lane & 7) * XSTB + (lane >> 4) * 16;
        const uint32_t boffc = (lane >> 4) * (8 * WSTB) + (lane & 7) * WSTB + ((lane >> 3) & 1) * 16;
        const uint32_t xlaneA = sbase + wa * 32 * XSTB + aoffc;
        const uint32_t blaneB = sbase + W1OFF + hb * (8 * WSTB) + boffc;

        const int rA = lane >> 2;
        const int qq = (lane & 3) * 2;

        uint2 ph[8];
        int t = blockIdx.x;   // grid <= ntiles

        __syncthreads();   // W1 staged

        // ---- prologue: buf0 <- chunk0(t); ph <- chunk1(t)
        #pragma unroll
        for (int i = 0; i < 8; i++) {
            int grow = t * 128 + rbw + i * 2;
            float4 v = (grow < N) ? x4[(size_t)grow * 64 + ldq]
                                  : make_float4(0.f, 0.f, 0.f, 0.f);
            half2 h0 = __floats2half2_rn(v.x, v.y);
            half2 h1 = __floats2half2_rn(v.z, v.w);
            *(uint2*)(smem + (rbw + i * 2) * XSTB + ldq * 8) =
                make_uint2(*(uint32_t*)&h0, *(uint32_t*)&h1);
        }
        #pragma unroll
        for (int i = 0; i < 8; i++) {
            int grow = t * 128 + rbw + i * 2;
            float4 v = (grow < N) ? x4[(size_t)grow * 64 + 16 + ldq]
                                  : make_float4(0.f, 0.f, 0.f, 0.f);
            half2 h0 = __floats2half2_rn(v.x, v.y);
            half2 h1 = __floats2half2_rn(v.z, v.w);
            ph[i] = make_uint2(*(uint32_t*)&h0, *(uint32_t*)&h1);
        }
        bar_pair(barid);

        while (t < ntiles) {
            const int rowBase = t * 128;
            uint32_t acc[8][2][2];
            #pragma unroll
            for (int i = 0; i < 8; i++)
                #pragma unroll
                for (int g = 0; g < 2; g++) { acc[i][g][0] = 0u; acc[i][g][1] = 0u; }

            #pragma unroll
            for (int kc = 0; kc < 4; kc++) {
                const int cur = kc & 1;
                int t1 = t; if (kc == 3) t1 = t + stride;
                if (t1 < ntiles) {
                    char* xb = smem + (((kc + 1) & 1) * XBUFB);
                    #pragma unroll
                    for (int i = 0; i < 8; i++)
                        *(uint2*)(xb + (rbw + i * 2) * XSTB + ldq * 8) = ph[i];
                }
                int t2 = t, c2 = kc + 2;
                if (kc >= 2) { t2 = t + stride; c2 = kc - 2; }
                if (t2 < ntiles) {
                    int rb2 = t2 * 128;
                    #pragma unroll
                    for (int i = 0; i < 8; i++) {
                        int grow = rb2 + rbw + i * 2;
                        float4 v = (grow < N) ? x4[(size_t)grow * 64 + c2 * 16 + ldq]
                                              : make_float4(0.f, 0.f, 0.f, 0.f);
                        half2 h0 = __floats2half2_rn(v.x, v.y);
                        half2 h1 = __floats2half2_rn(v.z, v.w);
                        ph[i] = make_uint2(*(uint32_t*)&h0, *(uint32_t*)&h1);
                    }
                }
                const uint32_t xab = xlaneA + cur * XBUFB;
                const uint32_t bab = blaneB + kc * 128;
                uint32_t bfc[4], bfn[4];
                ldm4(bfc, bab);
                #pragma unroll
                for (int ks8 = 0; ks8 < 4; ks8++) {
                    uint32_t a0[4], a1[4];
                    ldm4(a0, xab + ks8 * 32);
                    ldm4(a1, xab + ks8 * 32 + 16 * XSTB);
                    #pragma unroll
                    for (int ntp = 0; ntp < 4; ntp++) {
                        if (ntp < 3)
                            ldm4(bfn, bab + ks8 * 32 + (ntp + 1) * (16 * WSTB));
                        else if (ks8 < 3)
                            ldm4(bfn, bab + (ks8 + 1) * 32);
                        mma16816h(acc[2*ntp    ][0], a0, bfc[0], bfc[1]);
                        mma16816h(acc[2*ntp    ][1], a1, bfc[0], bfc[1]);
                        mma16816h(acc[2*ntp + 1][0], a0, bfc[2], bfc[3]);
                        mma16816h(acc[2*ntp + 1][1], a1, bfc[2], bfc[3]);
                        bfc[0] = bfn[0]; bfc[1] = bfn[1];
                        bfc[2] = bfn[2]; bfc[3] = bfn[3];
                    }
                }
                bar_pair(barid);
            }

            // Epilogue
            float yv[2][2] = {{0.f,0.f},{0.f,0.f}};
            float zv[2][2] = {{0.f,0.f},{0.f,0.f}};
            #pragma unroll
            for (int nt = 0; nt < 8; nt++) {
                const int h0i = (hb + nt) * 8 + qq;
                const int h1i = h0i + 1;
                const float bb0 = sb1[h0i], wa0 = sw2[2*h0i], wb0 = sw2[2*h0i + 1];
                const float bb1 = sb1[h1i], wa1 = sw2[2*h1i], wb1 = sw2[2*h1i + 1];
                #pragma unroll
                for (int g = 0; g < 2; g++) {
                    float2 f0 = __half22float2(*(half2*)&acc[nt][g][0]);
                    float2 f1 = __half22float2(*(half2*)&acc[nt][g][1]);
                    float t00 = tanh_approx(f0.x + bb0);
                    float t01 = tanh_approx(f0.y + bb1);
                    float t10 = tanh_approx(f1.x + bb0);
                    float t11 = tanh_approx(f1.y + bb1);
                    yv[g][0] += t00 * wa0 + t01 * wa1;
                    zv[g][0] += t00 * wb0 + t01 * wb1;
                    yv[g][1] += t10 * wa0 + t11 * wa1;
                    zv[g][1] += t10 * wb0 + t11 * wb1;
                }
            }
            #pragma unroll
            for (int o = 1; o < 4; o <<= 1) {
                #pragma unroll
                for (int g = 0; g < 2; g++) {
                    yv[g][0] += __shfl_xor_sync(0xffffffff, yv[g][0], o);
                    zv[g][0] += __shfl_xor_sync(0xffffffff, zv[g][0], o);
                    yv[g][1] += __shfl_xor_sync(0xffffffff, yv[g][1], o);
                    zv[g][1] += __shfl_xor_sync(0xffffffff, zv[g][1], o);
                }
            }
            if (w >= 4 && (lane & 3) == 0) {
                #pragma unroll
                for (int g = 0; g < 2; g++) {
                    sEp[wa*32 + g*16 + rA    ] = make_float2(yv[g][0], zv[g][0]);
                    sEp[wa*32 + g*16 + rA + 8] = make_float2(yv[g][1], zv[g][1]);
                }
            }
            bar_pair(barid);
            if (w < 4 && (lane & 3) == 0) {
                #pragma unroll
                for (int g = 0; g < 2; g++) {
                    float2 e0 = sEp[wa*32 + g*16 + rA];
                    float2 e1 = sEp[wa*32 + g*16 + rA + 8];
                    int gr0 = rowBase + wa*32 + g*16 + rA;
                    int gr1 = gr0 + 8;
                    if (gr0 < N) { g_y[gr0] = yv[g][0] + e0.x + B20; g_z[gr0] = zv[g][0] + e0.y + B21; }
                    if (gr1 < N) { g_y[gr1] = yv[g][1] + e1.x + B20; g_z[gr1] = zv[g][1] + e1.y + B21; }
                }
            }
            t += stride;
        }
    }

    // ================= GLOBAL BARRIER (replay-safe, monotonic) =============
    __shared__ int sepoch;
    __syncthreads();
    __threadfence();
    if (tid == 0) {
        int old = atomicAdd(&g_sync0, 1);
        int ep = old / gridDim.x + 1;
        sepoch = ep;
        int tgt = ep * gridDim.x;
        while (atomicAdd(&g_sync0, 0) < tgt) __nanosleep(64);
    }
    __syncthreads();
    __threadfence();
    const int epoch = sepoch;

    // ======================= PHASE 2: SEGMENT STATS =======================
    {
        float* sred = (float*)smem;                 // [256]
        float* sbc  = (float*)(smem + 1024);        // [3]
        int*   slen = (int*)(smem + 1040);          // [S_MAX]

        if (tid < S_MAX) slen[tid] = (tid < S) ? lengths[tid] : 0;
        __syncthreads();
        #pragma unroll
        for (int d = 1; d < S_MAX; d <<= 1) {
            int v = 0;
            if (tid < S_MAX && tid >= d) v = slen[tid - d];
            __syncthreads();
            if (tid < S_MAX) slen[tid] += v;
            __syncthreads();
        }

        for (int s = blockIdx.x; s < S; s += gridDim.x) {
            const int off = (s == 0) ? 0 : slen[s - 1];
            const int len = lengths[s];
            const float invlen = 1.0f / (float)len;

            float wsum = 0.f, wx = 0.f, zs = 0.f;
            for (int i = tid; i < len; i += 256) {
                float wv = __expf(g_y[off + i]);
                wsum += wv;
                wx   += wv * ((float)(i + 1) * invlen);
                zs   += g_z[off + i];
            }
            sred[tid] = wsum; __syncthreads();
            for (int o = 128; o > 0; o >>= 1) { if (tid < o) sred[tid] += sred[tid+o]; __syncthreads(); }
            if (tid == 0) sbc[0] = sred[0];
            __syncthreads();
            sred[tid] = wx; __syncthreads();
            for (int o = 128; o > 0; o >>= 1) { if (tid < o) sred[tid] += sred[tid+o]; __syncthreads(); }
            if (tid == 0) sbc[1] = sred[0];
            __syncthreads();
            sred[tid] = zs; __syncthreads();
            for (int o = 128; o > 0; o >>= 1) { if (tid < o) sred[tid] += sred[tid+o]; __syncthreads(); }
            if (tid == 0) sbc[2] = sred[0];
            __syncthreads();

            const float mu = sbc[1] / sbc[0];
            const float v  = sbc[2] * invlen;
            const float sd = (v > 20.f) ? v : log1pf(expf(v));   // softplus
            const float invsd = 1.0f / sd;

            float ps = 0.f;
            for (int i = tid; i < len; i += 256) {
                float xp = (float)(i + 1) * invlen;
                float d = (xp - mu) * invsd;
                ps += __expf(-0.5f * d * d);
            }
            sred[tid] = ps; __syncthreads();
            for (int o = 128; o > 0; o >>= 1) { if (tid < o) sred[tid] += sred[tid+o]; __syncthreads(); }
            if (tid == 0) {
                float psum = sred[0] * (0.3989422804014327f * invsd);
                g_segp[s] = make_float4(mu, sd, psum, 0.f);
                g_offv[s] = off;
            }
            __syncthreads();
            __threadfence();
            if (tid == 0) atomicExch(&g_flag[s], epoch);   // publish ready
        }
    }

    // ================= PHASE 3: ATTN + OUT (per-seg flag wait) ============
    {
        float*  sattn = (float*)smem;                // [256]
        float4* sred4 = (float4*)(smem + 1024);      // [256]
        int*    slastp = (int*)(smem + 5120);

        const int g = tid >> 6;
        const int c = tid & 63;

        for (int unit = blockIdx.x; unit < S * NCH; unit += gridDim.x) {
            const int s = unit >> 3, ch = unit & 7;
            if (tid == 0) {
                while (atomicAdd(&g_flag[s], 0) < epoch) __nanosleep(64);
            }
            __syncthreads();
            __threadfence();

            const int len = lengths[s];
            const int off = g_offv[s];
            const float4 p = g_segp[s];
            const float mu = p.x, invsd = 1.0f / p.y, psum = p.z;
            const float invlen = 1.0f / (float)len;
            const float coef = 0.3989422804014327f * invsd / (psum + 0.001f);

            float4 acc = make_float4(0.f, 0.f, 0.f, 0.f);
            const int r0 = ch * CROWS;
            #pragma unroll
            for (int tb = 0; tb < CROWS; tb += 256) {
                const int tsz = (CROWS - tb < 256) ? (CROWS - tb) : 256;
                int rbase = r0 + tb;
                if (rbase >= len) break;
                int r = rbase + tid;
                float a = 0.f;
                if (tid < tsz && r < len) {
                    float xp = (float)(r + 1) * invlen;
                    float d = (xp - mu) * invsd;
                    a = __expf(-0.5f * d * d) * coef;
                    attn_out[off + r] = a;
                }
                sattn[tid] = a;
                __syncthreads();
                int nrows = len - rbase; if (nrows > tsz) nrows = tsz;
                const float4* __restrict__ xp4 = (const float4*)(x + (size_t)(off + rbase) * 256) + c;
                int j = g;
                for (; j + 28 < nrows; j += 32) {
                    float aa[8]; float4 vv[8];
                    #pragma unroll
                    for (int u = 0; u < 8; u++) { aa[u] = sattn[j + u*4]; vv[u] = xp4[(size_t)(j + u*4) * 64]; }
                    #pragma unroll
                    for (int u = 0; u < 8; u++) {
                        acc.x += aa[u] * vv[u].x; acc.y += aa[u] * vv[u].y;
                        acc.z += aa[u] * vv[u].z; acc.w += aa[u] * vv[u].w;
                    }
                }
                for (; j < nrows; j += 4) {
                    float a0 = sattn[j];
                    float4 v0 = xp4[(size_t)j * 64];
                    acc.x += a0 * v0.x; acc.y += a0 * v0.y; acc.z += a0 * v0.z; acc.w += a0 * v0.w;
                }
                __syncthreads();
            }
            sred4[tid] = acc;
            __syncthreads();
            if (g == 0) {
                float4 t0 = sred4[c], t1 = sred4[64 + c], t2 = sred4[128 + c], t3 = sred4[192 + c];
                float4 tot = make_float4(t0.x + t1.x + t2.x + t3.x,
                                         t0.y + t1.y + t2.y + t3.y,
                                         t0.z + t1.z + t2.z + t3.z,
                                         t0.w + t1.w + t2.w + t3.w);
                ((float4*)&g_part[(size_t)(s * NCH + ch) * 256])[c] = tot;
            }
            // fused finalize: last chunk of this segment sums partials
            __threadfence();
            if (tid == 0) {
                int old = atomicAdd(&g_cnt[s], 1);
                slastp[0] = (old == NCH - 1);
            }
            __syncthreads();
            if (slastp[0]) {
                float v = 0.f;
                #pragma unroll
                for (int j = 0; j < NCH; j++) v += g_part[(size_t)(s * NCH + j) * 256 + tid];
                out[(size_t)s * 256 + tid] = v;
                if (tid == 0) g_cnt[s] = 0;   // reset for next replay
            }
            __syncthreads();
        }
    }
}

// ---------------------------------------------------------------------------
extern "C" void kernel_launch(void* const* d_in, const int* in_sizes, int n_in,
                              void* d_out, int out_size)
{
    const float* x       = (const float*)d_in[0];
    const int*   lengths = (const int*)  d_in[1];
    const float* W1      = (const float*)d_in[2];
    const float* b1      = (const float*)d_in[3];
    const float* W2      = (const float*)d_in[4];
    const float* b2      = (const float*)d_in[5];

    const int N = in_sizes[0] / 256;
    const int S = in_sizes[1];

    float* out  = (float*)d_out;             // (S, 256)
    float* attn = out + (size_t)S * 256;     // (N, 1)

    cudaFuncSetAttribute(fused_kernel,
                         cudaFuncAttributeMaxDynamicSharedMemorySize, SMEM_K1);

    int ntiles = (N + 127) / 128;
    int grid = ntiles < 296 ? ntiles : 296;   // all blocks resident (2/SM)
    fused_kernel<<<grid, 256, SMEM_K1>>>(x, W1, b1, W2, b2, lengths,
                                         attn, out, N, ntiles, S);
}

// round 15
// speedup vs baseline: 1.2335x; 1.2335x over previous
#include <cuda_runtime.h>
#include <cuda_fp16.h>
#include <cstdint>

// Problem-shape maxima (S=128 segments, lengths in [1024,3072])
#define NMAX 393216
#define S_MAX 128
#define NCH 8          // attn chunks per segment
#define CROWS 384      // rows per attn chunk (8*384 = 3072 = max len)

__device__ float g_y[NMAX];
__device__ float g_z[NMAX];
__device__ float4 g_segp[S_MAX];
__device__ float g_part[S_MAX * NCH * 256];
__device__ int   g_cnt[S_MAX];    // zero-init; self-resetting per call
__device__ int   g_done[S_MAX];   // stats-ready flag; self-resetting per call

__device__ __forceinline__ float tanh_approx(float v) {
    float r;
    asm("tanh.approx.f32 %0, %1;" : "=f"(r) : "f"(v));
    return r;
}
__device__ __forceinline__ uint32_t smem_u32(const void* p) {
    uint32_t a;
    asm("{ .reg .u64 t; cvta.to.shared.u64 t, %1; cvt.u32.u64 %0, t; }" : "=r"(a) : "l"(p));
    return a;
}
__device__ __forceinline__ void ldm4(uint32_t* r, uint32_t addr) {
    asm volatile("ldmatrix.sync.aligned.m8n8.x4.shared.b16 {%0,%1,%2,%3}, [%4];"
        : "=r"(r[0]), "=r"(r[1]), "=r"(r[2]), "=r"(r[3]) : "r"(addr));
}
// f16-accumulate HMMA: C/D = 2 regs (f16x2)
__device__ __forceinline__ void mma16816h(uint32_t* c, const uint32_t* a,
                                          uint32_t b0, uint32_t b1) {
    asm volatile("mma.sync.aligned.m16n8k16.row.col.f16.f16.f16.f16 "
        "{%0,%1}, {%2,%3,%4,%5}, {%6,%7}, {%0,%1};"
        : "+r"(c[0]), "+r"(c[1])
        : "r"(a[0]), "r"(a[1]), "r"(a[2]), "r"(a[3]), "r"(b0), "r"(b1));
}
__device__ __forceinline__ void bar_pair(int id) {
    asm volatile("bar.sync %0, 64;" :: "r"(id) : "memory");
}

// ---------------------------------------------------------------------------
// Kernel 1 (R13 gemm, unchanged): persistent fused GEMM + head,
// HMMA f16-accum + ldmatrix, PAIR-DECOUPLED.
// ---------------------------------------------------------------------------
#define XSTB 144          // x row stride, bytes (64 halves + 8 pad)
#define WSTB 528          // W1 row stride, bytes (256 halves + 8 pad)
#define WST  264          // W1 row stride, halves
#define XBUFB (128 * XSTB)           // 18432 bytes per x buffer
#define W1OFF (2 * XBUFB)            // 36864
#define FOFF  (W1OFF + 128 * WSTB)   // 104448
#define SMEM_K1 (FOFF + 512 + 1024 + 1024)

__global__ __launch_bounds__(256, 2) void gemm_head_kernel(
    const float* __restrict__ x, const float* __restrict__ W1,
    const float* __restrict__ b1, const float* __restrict__ W2,
    const float* __restrict__ b2, int N, int ntiles)
{
    extern __shared__ char smem[];
    half*   w1s = (half*)(smem + W1OFF);
    float*  sb1 = (float*)(smem + FOFF);
    float*  sw2 = sb1 + 128;
    float2* sEp = (float2*)(sw2 + 256);

    const int tid  = threadIdx.x;
    const int lane = tid & 31;
    const int w    = tid >> 5;       // 0..7
    const int wa   = w & 3;          // pair id / A-row quarter
    const int hb   = (w >> 2) * 8;   // h-tile base (units of 8 columns)
    const int barid = 1 + wa;

    for (int idx = tid; idx < 256 * 128; idx += 256) {
        int k = idx >> 7, h = idx & 127;
        w1s[h * WST + k] = __float2half(W1[idx]);
    }
    if (tid < 128) sb1[tid] = b1[tid];
    sw2[tid] = W2[tid];

    const float B20 = __ldg(b2), B21 = __ldg(b2 + 1);
    const int stride = gridDim.x;
    const float4* __restrict__ x4 = (const float4*)x;

    const int rbw = wa * 32 + (w >> 2) * 16 + (lane >> 4);  // + i*2
    const int ldq = lane & 15;

    const uint32_t sbase = smem_u32(smem);
    const uint32_t aoffc = ((lane >> 3) & 1) * (8 * XSTB) + (lane & 7) * XSTB + (lane >> 4) * 16;
    const uint32_t boffc = (lane >> 4) * (8 * WSTB) + (lane & 7) * WSTB + ((lane >> 3) & 1) * 16;
    const uint32_t xlaneA = sbase + wa * 32 * XSTB + aoffc;
    const uint32_t blaneB = sbase + W1OFF + hb * (8 * WSTB) + boffc;

    const int rA = lane >> 2;
    const int qq = (lane & 3) * 2;

    uint2 ph[8];
    int t = blockIdx.x;   // grid <= ntiles

    __syncthreads();   // W1 staged (only block-wide sync)

    #pragma unroll
    for (int i = 0; i < 8; i++) {
        int grow = t * 128 + rbw + i * 2;
        float4 v = (grow < N) ? x4[(size_t)grow * 64 + ldq]
                              : make_float4(0.f, 0.f, 0.f, 0.f);
        half2 h0 = __floats2half2_rn(v.x, v.y);
        half2 h1 = __floats2half2_rn(v.z, v.w);
        *(uint2*)(smem + (rbw + i * 2) * XSTB + ldq * 8) =
            make_uint2(*(uint32_t*)&h0, *(uint32_t*)&h1);
    }
    #pragma unroll
    for (int i = 0; i < 8; i++) {
        int grow = t * 128 + rbw + i * 2;
        float4 v = (grow < N) ? x4[(size_t)grow * 64 + 16 + ldq]
                              : make_float4(0.f, 0.f, 0.f, 0.f);
        half2 h0 = __floats2half2_rn(v.x, v.y);
        half2 h1 = __floats2half2_rn(v.z, v.w);
        ph[i] = make_uint2(*(uint32_t*)&h0, *(uint32_t*)&h1);
    }
    bar_pair(barid);

    while (t < ntiles) {
        const int rowBase = t * 128;
        uint32_t acc[8][2][2];
        #pragma unroll
        for (int i = 0; i < 8; i++)
            #pragma unroll
            for (int g = 0; g < 2; g++) { acc[i][g][0] = 0u; acc[i][g][1] = 0u; }

        #pragma unroll
        for (int kc = 0; kc < 4; kc++) {
            const int cur = kc & 1;
            int t1 = t; if (kc == 3) t1 = t + stride;
            if (t1 < ntiles) {
                char* xb = smem + (((kc + 1) & 1) * XBUFB);
                #pragma unroll
                for (int i = 0; i < 8; i++)
                    *(uint2*)(xb + (rbw + i * 2) * XSTB + ldq * 8) = ph[i];
            }
            int t2 = t, c2 = kc + 2;
            if (kc >= 2) { t2 = t + stride; c2 = kc - 2; }
            if (t2 < ntiles) {
                int rb2 = t2 * 128;
                #pragma unroll
                for (int i = 0; i < 8; i++) {
                    int grow = rb2 + rbw + i * 2;
                    float4 v = (grow < N) ? x4[(size_t)grow * 64 + c2 * 16 + ldq]
                                          : make_float4(0.f, 0.f, 0.f, 0.f);
                    half2 h0 = __floats2half2_rn(v.x, v.y);
                    half2 h1 = __floats2half2_rn(v.z, v.w);
                    ph[i] = make_uint2(*(uint32_t*)&h0, *(uint32_t*)&h1);
                }
            }
            const uint32_t xab = xlaneA + cur * XBUFB;
            const uint32_t bab = blaneB + kc * 128;
            uint32_t bfc[4], bfn[4];
            ldm4(bfc, bab);
            #pragma unroll
            for (int ks8 = 0; ks8 < 4; ks8++) {
                uint32_t a0[4], a1[4];
                ldm4(a0, xab + ks8 * 32);
                ldm4(a1, xab + ks8 * 32 + 16 * XSTB);
                #pragma unroll
                for (int ntp = 0; ntp < 4; ntp++) {
                    if (ntp < 3)
                        ldm4(bfn, bab + ks8 * 32 + (ntp + 1) * (16 * WSTB));
                    else if (ks8 < 3)
                        ldm4(bfn, bab + (ks8 + 1) * 32);
                    mma16816h(acc[2*ntp    ][0], a0, bfc[0], bfc[1]);
                    mma16816h(acc[2*ntp    ][1], a1, bfc[0], bfc[1]);
                    mma16816h(acc[2*ntp + 1][0], a0, bfc[2], bfc[3]);
                    mma16816h(acc[2*ntp + 1][1], a1, bfc[2], bfc[3]);
                    bfc[0] = bfn[0]; bfc[1] = bfn[1];
                    bfc[2] = bfn[2]; bfc[3] = bfn[3];
                }
            }
            bar_pair(barid);
        }

        float yv[2][2] = {{0.f,0.f},{0.f,0.f}};
        float zv[2][2] = {{0.f,0.f},{0.f,0.f}};
        #pragma unroll
        for (int nt = 0; nt < 8; nt++) {
            const int h0i = (hb + nt) * 8 + qq;
            const int h1i = h0i + 1;
            const float bb0 = sb1[h0i], wa0 = sw2[2*h0i], wb0 = sw2[2*h0i + 1];
            const float bb1 = sb1[h1i], wa1 = sw2[2*h1i], wb1 = sw2[2*h1i + 1];
            #pragma unroll
            for (int g = 0; g < 2; g++) {
                float2 f0 = __half22float2(*(half2*)&acc[nt][g][0]);
                float2 f1 = __half22float2(*(half2*)&acc[nt][g][1]);
                float t00 = tanh_approx(f0.x + bb0);
                float t01 = tanh_approx(f0.y + bb1);
                float t10 = tanh_approx(f1.x + bb0);
                float t11 = tanh_approx(f1.y + bb1);
                yv[g][0] += t00 * wa0 + t01 * wa1;
                zv[g][0] += t00 * wb0 + t01 * wb1;
                yv[g][1] += t10 * wa0 + t11 * wa1;
                zv[g][1] += t10 * wb0 + t11 * wb1;
            }
        }
        #pragma unroll
        for (int o = 1; o < 4; o <<= 1) {
            #pragma unroll
            for (int g = 0; g < 2; g++) {
                yv[g][0] += __shfl_xor_sync(0xffffffff, yv[g][0], o);
                zv[g][0] += __shfl_xor_sync(0xffffffff, zv[g][0], o);
                yv[g][1] += __shfl_xor_sync(0xffffffff, yv[g][1], o);
                zv[g][1] += __shfl_xor_sync(0xffffffff, zv[g][1], o);
            }
        }
        if (w >= 4 && (lane & 3) == 0) {
            #pragma unroll
            for (int g = 0; g < 2; g++) {
                sEp[wa*32 + g*16 + rA    ] = make_float2(yv[g][0], zv[g][0]);
                sEp[wa*32 + g*16 + rA + 8] = make_float2(yv[g][1], zv[g][1]);
            }
        }
        bar_pair(barid);
        if (w < 4 && (lane & 3) == 0) {
            #pragma unroll
            for (int g = 0; g < 2; g++) {
                float2 e0 = sEp[wa*32 + g*16 + rA];
                float2 e1 = sEp[wa*32 + g*16 + rA + 8];
                int gr0 = rowBase + wa*32 + g*16 + rA;
                int gr1 = gr0 + 8;
                if (gr0 < N) { g_y[gr0] = yv[g][0] + e0.x + B20; g_z[gr0] = zv[g][0] + e0.y + B21; }
                if (gr1 < N) { g_y[gr1] = yv[g][1] + e1.x + B20; g_z[gr1] = zv[g][1] + e1.y + B21; }
            }
        }
        t += stride;
    }
}

// ---------------------------------------------------------------------------
// Kernel 2 (merged stats + attn + out): grid (NCH, S), 256 threads.
//   Block (0, s) first computes segment-s stats (no-ymax 2-pass, parallel
//   offset scan, MUFU exp) and publishes g_done[s]=1. Every block (ch, s)
//   spin-waits on g_done[s], then computes attn rows + its partial of
//   seg_sum(attn*x). Fused finalize: the LAST of the NCH blocks (g_cnt)
//   sums partials into out and resets g_cnt[s] AND g_done[s] (all waiters
//   have passed the flag by then) -- replay-safe under graph capture.
//   Stats for segment s overlaps attn for other segments.
// ---------------------------------------------------------------------------
__global__ __launch_bounds__(256) void stats_attn_kernel(
    const float* __restrict__ x, const int* __restrict__ lengths,
    float* __restrict__ attn_out, float* __restrict__ out, int S)
{
    __shared__ float  sattn[256];       // also reused as sred for stats
    __shared__ float4 sred4[256];
    __shared__ int    slen[S_MAX];
    __shared__ float  sbc[4];
    __shared__ int    slast;

    const int s = blockIdx.y, ch = blockIdx.x;
    const int tid = threadIdx.x;

    // ---- offsets via parallel scan (every block; cheap)
    if (tid < S_MAX) slen[tid] = (tid < S) ? lengths[tid] : 0;
    __syncthreads();
    #pragma unroll
    for (int d = 1; d < S_MAX; d <<= 1) {
        int v = 0;
        if (tid < S_MAX && tid >= d) v = slen[tid - d];
        __syncthreads();
        if (tid < S_MAX) slen[tid] += v;
        __syncthreads();
    }
    const int off = (s == 0) ? 0 : slen[s - 1];
    const int len = lengths[s];
    const float invlen = 1.0f / (float)len;

    float mu, invsd, psum;

    if (ch == 0) {
        // ======== stats for this segment ========
        float* sred = sattn;
        float wsum = 0.f, wx = 0.f, zs = 0.f;
        for (int i = tid; i < len; i += 256) {
            float wv = __expf(g_y[off + i]);
            wsum += wv;
            wx   += wv * ((float)(i + 1) * invlen);
            zs   += g_z[off + i];
        }
        sred[tid] = wsum; __syncthreads();
        for (int o = 128; o > 0; o >>= 1) { if (tid < o) sred[tid] += sred[tid+o]; __syncthreads(); }
        if (tid == 0) sbc[0] = sred[0];
        __syncthreads();
        sred[tid] = wx; __syncthreads();
        for (int o = 128; o > 0; o >>= 1) { if (tid < o) sred[tid] += sred[tid+o]; __syncthreads(); }
        if (tid == 0) sbc[1] = sred[0];
        __syncthreads();
        sred[tid] = zs; __syncthreads();
        for (int o = 128; o > 0; o >>= 1) { if (tid < o) sred[tid] += sred[tid+o]; __syncthreads(); }
        if (tid == 0) sbc[2] = sred[0];
        __syncthreads();

        const float mu_ = sbc[1] / sbc[0];
        const float v   = sbc[2] * invlen;
        const float sd  = (v > 20.f) ? v : log1pf(expf(v));   // softplus
        const float isd = 1.0f / sd;

        float ps = 0.f;
        for (int i = tid; i < len; i += 256) {
            float xp = (float)(i + 1) * invlen;
            float d = (xp - mu_) * isd;
            ps += __expf(-0.5f * d * d);
        }
        sred[tid] = ps; __syncthreads();
        for (int o = 128; o > 0; o >>= 1) { if (tid < o) sred[tid] += sred[tid+o]; __syncthreads(); }
        if (tid == 0) {
            float psum_ = sred[0] * (0.3989422804014327f * isd);
            g_segp[s] = make_float4(mu_, sd, psum_, 0.f);
            __threadfence();
            atomicExch(&g_done[s], 1);   // publish
            sbc[0] = mu_; sbc[1] = isd; sbc[2] = psum_;
        }
        __syncthreads();
        mu = sbc[0]; invsd = sbc[1]; psum = sbc[2];
    } else {
        // ======== wait for this segment's stats ========
        if (tid == 0) {
            while (atomicAdd(&g_done[s], 0) == 0) __nanosleep(64);
            float4 p = g_segp[s];
            sbc[0] = p.x; sbc[1] = 1.0f / p.y; sbc[2] = p.z;
        }
        __syncthreads();
        mu = sbc[0]; invsd = sbc[1]; psum = sbc[2];
    }

    const float coef = 0.3989422804014327f * invsd / (psum + 0.001f);
    const int g = tid >> 6;
    const int c = tid & 63;

    float4 acc = make_float4(0.f, 0.f, 0.f, 0.f);
    const int r0 = ch * CROWS;
    #pragma unroll
    for (int tb = 0; tb < CROWS; tb += 256) {
        const int tsz = (CROWS - tb < 256) ? (CROWS - tb) : 256;
        int rbase = r0 + tb;
        if (rbase >= len) break;
        int r = rbase + tid;
        float a = 0.f;
        if (tid < tsz && r < len) {
            float xp = (float)(r + 1) * invlen;
            float d = (xp - mu) * invsd;
            a = __expf(-0.5f * d * d) * coef;
            attn_out[off + r] = a;
        }
        sattn[tid] = a;
        __syncthreads();
        int nrows = len - rbase; if (nrows > tsz) nrows = tsz;
        const float4* __restrict__ xp4 = (const float4*)(x + (size_t)(off + rbase) * 256) + c;
        int j = g;
        for (; j + 28 < nrows; j += 32) {
            float aa[8]; float4 vv[8];
            #pragma unroll
            for (int u = 0; u < 8; u++) { aa[u] = sattn[j + u*4]; vv[u] = xp4[(size_t)(j + u*4) * 64]; }
            #pragma unroll
            for (int u = 0; u < 8; u++) {
                acc.x += aa[u] * vv[u].x; acc.y += aa[u] * vv[u].y;
                acc.z += aa[u] * vv[u].z; acc.w += aa[u] * vv[u].w;
            }
        }
        for (; j < nrows; j += 4) {
            float a0 = sattn[j];
            float4 v0 = xp4[(size_t)j * 64];
            acc.x += a0 * v0.x; acc.y += a0 * v0.y; acc.z += a0 * v0.z; acc.w += a0 * v0.w;
        }
        __syncthreads();
    }
    sred4[tid] = acc;
    __syncthreads();
    if (g == 0) {
        float4 t0 = sred4[c], t1 = sred4[64 + c], t2 = sred4[128 + c], t3 = sred4[192 + c];
        float4 tot = make_float4(t0.x + t1.x + t2.x + t3.x,
                                 t0.y + t1.y + t2.y + t3.y,
                                 t0.z + t1.z + t2.z + t3.z,
                                 t0.w + t1.w + t2.w + t3.w);
        ((float4*)&g_part[(size_t)(s * NCH + ch) * 256])[c] = tot;
    }
    // ---- fused finalize: last chunk-block of this segment sums partials
    __threadfence();
    if (tid == 0) {
        int old = atomicAdd(&g_cnt[s], 1);
        slast = (old == NCH - 1);
    }
    __syncthreads();
    if (slast) {
        float v = 0.f;
        #pragma unroll
        for (int j = 0; j < NCH; j++) v += g_part[(size_t)(s * NCH + j) * 256 + tid];
        out[(size_t)s * 256 + tid] = v;
        if (tid == 0) {
            g_cnt[s] = 0;              // reset for next graph replay
            atomicExch(&g_done[s], 0); // all waiters have passed; safe reset
        }
    }
}

// ---------------------------------------------------------------------------
extern "C" void kernel_launch(void* const* d_in, const int* in_sizes, int n_in,
                              void* d_out, int out_size)
{
    const float* x       = (const float*)d_in[0];
    const int*   lengths = (const int*)  d_in[1];
    const float* W1      = (const float*)d_in[2];
    const float* b1      = (const float*)d_in[3];
    const float* W2      = (const float*)d_in[4];
    const float* b2      = (const float*)d_in[5];

    const int N = in_sizes[0] / 256;
    const int S = in_sizes[1];

    float* out  = (float*)d_out;             // (S, 256)
    float* attn = out + (size_t)S * 256;     // (N, 1)

    cudaFuncSetAttribute(gemm_head_kernel,
                         cudaFuncAttributeMaxDynamicSharedMemorySize, SMEM_K1);

    int ntiles = (N + 127) / 128;
    int grid = ntiles < 296 ? ntiles : 296;   // 2 blocks/SM persistent
    gemm_head_kernel<<<grid, 256, SMEM_K1>>>(x, W1, b1, W2, b2, N, ntiles);
    stats_attn_kernel<<<dim3(NCH, S), 256>>>(x, lengths, attn, out, S);
}